// round 11
// baseline (speedup 1.0000x reference)
#include <cuda_runtime.h>
#include <cuda_bf16.h>
#include <cstdint>

#define NB   8
#define NC   256
#define NH   128
#define NW   128
#define NG   32
#define CPG  8
#define NOUT 256
#define FEPS 1e-5f
#define HWSZ (NH * NW)

// ---------------- device scratch (no-alloc rule: __device__ globals) --------
// y split into bf16 hi/lo, channel-pair packed: uint2 {x = hi pair, y = lo pair}
// layout [b][c2=0..127][pix]
__device__ uint2    g_y2[(size_t)NB * 128 * HWSZ];
__device__ float    g_mean[NB * NC];
__device__ float    g_rstd[NB * NC];
// conv weights pre-permuted into per-thread fragment chunks:
// [tap][cichunk][half][2048 words], word idx = ((((kk*4+k2l)*2+n0h)*4+ntpair)*8+lq)*4+widx
__device__ uint32_t g_wBh[9 * 8 * 2 * 2048];
__device__ uint32_t g_wBl[9 * 8 * 2 * 2048];

__device__ __forceinline__ int refl(int i, int n) {
    return i < 0 ? -i : (i >= n ? 2 * n - 2 - i : i);
}

__device__ __forceinline__ void mma16816(float* c, const uint32_t* a,
                                         uint32_t b0, uint32_t b1) {
    asm volatile(
        "mma.sync.aligned.m16n8k16.row.col.f32.bf16.bf16.f32 "
        "{%0,%1,%2,%3}, {%4,%5,%6,%7}, {%8,%9}, {%0,%1,%2,%3};"
        : "+f"(c[0]), "+f"(c[1]), "+f"(c[2]), "+f"(c[3])
        : "r"(a[0]), "r"(a[1]), "r"(a[2]), "r"(a[3]), "r"(b0), "r"(b1));
}

// ============================================================================
// Kernel 1: per-(b,c) mean / rstd over 128x128 (biased variance)
// ============================================================================
__global__ __launch_bounds__(256) void stats_kernel(const float* __restrict__ x) {
    __shared__ float sh[16];
    int bc = blockIdx.x;
    const float4* xc = reinterpret_cast<const float4*>(x + (size_t)bc * HWSZ);
    float s = 0.f, ss = 0.f;
    for (int i = threadIdx.x; i < HWSZ / 4; i += 256) {
        float4 v = xc[i];
        s  += (v.x + v.y) + (v.z + v.w);
        ss += (v.x * v.x + v.y * v.y) + (v.z * v.z + v.w * v.w);
    }
    #pragma unroll
    for (int o = 16; o > 0; o >>= 1) {
        s  += __shfl_down_sync(0xffffffffu, s,  o);
        ss += __shfl_down_sync(0xffffffffu, ss, o);
    }
    if ((threadIdx.x & 31) == 0) {
        sh[threadIdx.x >> 5]       = s;
        sh[8 + (threadIdx.x >> 5)] = ss;
    }
    __syncthreads();
    if (threadIdx.x == 0) {
        float S = 0.f, SS = 0.f;
        #pragma unroll
        for (int i = 0; i < 8; i++) { S += sh[i]; SS += sh[8 + i]; }
        float m   = S * (1.f / HWSZ);
        float var = SS * (1.f / HWSZ) - m * m;
        g_mean[bc] = m;
        g_rstd[bc] = rsqrtf(var + FEPS);
    }
}

// ============================================================================
// Kernel 1b: split + permute final-conv weights into fragment-chunk order.
// 16B chunk = {w(c2b,coA), w(c2b+4,coA), w(c2b,coA+1), w(c2b+4,coA+1)} with
// co mapping: co = half*128 + n0h*64 + ntpair*16 + 2*lq + (widx>>1).
// ============================================================================
__global__ __launch_bounds__(256) void wprep_kernel(const float* __restrict__ conv_w) {
    int tap     = blockIdx.x;   // 0..8
    int cichunk = blockIdx.y;   // 0..7
    int half    = blockIdx.z;   // 0..1
    size_t base = ((size_t)(tap * 8 + cichunk) * 2 + half) * 2048;
    for (int w = threadIdx.x; w < 2048; w += 256) {
        int widx   = w & 3;
        int lq     = (w >> 2) & 7;
        int ntpair = (w >> 5) & 3;
        int n0h    = (w >> 7) & 1;
        int k2l    = (w >> 8) & 3;
        int kk     = (w >> 10) & 1;
        int c2 = cichunk * 16 + kk * 8 + k2l + ((widx & 1) ? 4 : 0);
        int co = half * 128 + n0h * 64 + ntpair * 16 + 2 * lq + (widx >> 1);
        float w0 = conv_w[((size_t)co * NC + 2 * c2)     * 9 + tap];
        float w1 = conv_w[((size_t)co * NC + 2 * c2 + 1) * 9 + tap];
        __nv_bfloat16 h0 = __float2bfloat16(w0);
        __nv_bfloat16 h1 = __float2bfloat16(w1);
        __nv_bfloat16 l0 = __float2bfloat16(w0 - __bfloat162float(h0));
        __nv_bfloat16 l1 = __float2bfloat16(w1 - __bfloat162float(h1));
        g_wBh[base + w] = (uint32_t)__bfloat16_as_ushort(h0) |
                          ((uint32_t)__bfloat16_as_ushort(h1) << 16);
        g_wBl[base + w] = (uint32_t)__bfloat16_as_ushort(l0) |
                          ((uint32_t)__bfloat16_as_ushort(l1) << 16);
    }
}

// ============================================================================
// Kernel 2: fused instance-norm + adaptive grouped 3x3 + folded 1x1 + bias,
//           emitting channel-pair-packed bf16 {hi,lo} uint2.
// ============================================================================
__global__ __launch_bounds__(256, 2) void ada_kernel(
    const float* __restrict__ x,
    const float* __restrict__ ws,    // [B,C,CPG,3,3]
    const float* __restrict__ wp,    // [B,C,CPG,1,1]
    const float* __restrict__ bias)  // [B,C]
{
    __shared__ float tile[CPG][10][132];
    __shared__ float sW[CPG][CPG][9];

    int rt = blockIdx.x;   // 0..15
    int g  = blockIdx.y;
    int b  = blockIdx.z;
    int r0 = rt * 8;
    int t  = threadIdx.x;
    int cbase = b * NC + g * CPG;
    const float* xb = x + (size_t)cbase * HWSZ;

    for (int e = t; e < CPG * CPG * 9; e += 256) {
        int o = e / 72, rem = e % 72, i = rem / 9, k = rem % 9;
        float acc = 0.f;
        #pragma unroll
        for (int m = 0; m < CPG; m++)
            acc += wp[(size_t)(cbase + o) * CPG + m] *
                   ws[((size_t)(cbase + m) * CPG + i) * 9 + k];
        sW[o][i][k] = acc;
    }

    for (int e = t; e < CPG * 10 * 130; e += 256) {
        int ch = e / 1300, rem = e % 1300, tr = rem / 130, tc = rem % 130;
        int gr = refl(r0 - 1 + tr, NH);
        int gc = refl(tc - 1, NW);
        float m  = g_mean[cbase + ch];
        float rs = g_rstd[cbase + ch];
        tile[ch][tr][tc] = (xb[(size_t)ch * HWSZ + gr * NW + gc] - m) * rs;
    }
    __syncthreads();

    int col = t & 127;
    int rq  = t >> 7;
    float acc[CPG][4];
    #pragma unroll
    for (int o = 0; o < CPG; o++)
        #pragma unroll
        for (int r = 0; r < 4; r++) acc[o][r] = 0.f;

    #pragma unroll 1
    for (int i = 0; i < CPG; i++) {
        float v[6][3];
        #pragma unroll
        for (int rr = 0; rr < 6; rr++)
            #pragma unroll
            for (int c3 = 0; c3 < 3; c3++)
                v[rr][c3] = tile[i][rq * 4 + rr][col + c3];
        #pragma unroll
        for (int o = 0; o < CPG; o++) {
            #pragma unroll
            for (int k = 0; k < 9; k++) {
                float w = sW[o][i][k];
                int dy = k / 3, dx = k % 3;
                #pragma unroll
                for (int r = 0; r < 4; r++)
                    acc[o][r] += w * v[r + dy][dx];
            }
        }
    }

    int ccg = g * CPG;
    #pragma unroll
    for (int o = 0; o < CPG; o += 2) {
        float b0v = bias[cbase + o], b1v = bias[cbase + o + 1];
        int c2 = (ccg + o) >> 1;
        #pragma unroll
        for (int r = 0; r < 4; r++) {
            float v0 = acc[o][r] + b0v;
            float v1 = acc[o + 1][r] + b1v;
            __nv_bfloat16 h0 = __float2bfloat16(v0);
            __nv_bfloat16 h1 = __float2bfloat16(v1);
            __nv_bfloat16 l0 = __float2bfloat16(v0 - __bfloat162float(h0));
            __nv_bfloat16 l1 = __float2bfloat16(v1 - __bfloat162float(h1));
            uint2 pk;
            pk.x = (uint32_t)__bfloat16_as_ushort(h0) |
                   ((uint32_t)__bfloat16_as_ushort(h1) << 16);
            pk.y = (uint32_t)__bfloat16_as_ushort(l0) |
                   ((uint32_t)__bfloat16_as_ushort(l1) << 16);
            g_y2[((size_t)(b * 128 + c2)) * HWSZ +
                 (size_t)(r0 + rq * 4 + r) * NW + col] = pk;
        }
    }
}

// ============================================================================
// Kernel 3: final 3x3 conv via mma.sync m16n8k16 bf16, 3-term split.
// CTA = (row r, co-half, batch). D[128 pixels][128 co]. 8 warps = 4(M) x 2(N).
// A: im2col per 32-ci chunk, c2-stride 408 (conflict-free frag LDS).
// B: GMEM pre-permuted chunks -> linear copy -> conflict-free LDS.128,
//    double-buffered, ONE __syncthreads per tap.
// ============================================================================
#define A_STRIDE 408
#define A_WORDS  (16 * A_STRIDE)                  // 6528
#define B_BUF_WORDS 4096                          // hi 2048 + lo 2048
#define CONV_SMEM ((2 * A_WORDS + 2 * B_BUF_WORDS) * 4)   // 84992 bytes

extern __shared__ uint32_t s_cv[];

__device__ __forceinline__ void stageB(int tap, int chunk, int half,
                                       uint32_t* dst, int t) {
    const uint4* srcH = reinterpret_cast<const uint4*>(
        g_wBh + ((size_t)(tap * 8 + chunk) * 2 + half) * 2048);
    const uint4* srcL = reinterpret_cast<const uint4*>(
        g_wBl + ((size_t)(tap * 8 + chunk) * 2 + half) * 2048);
    uint4* dH = reinterpret_cast<uint4*>(dst);
    uint4* dL = reinterpret_cast<uint4*>(dst + 2048);
    #pragma unroll
    for (int i = 0; i < 2; i++) {
        dH[t + i * 256] = srcH[t + i * 256];
        dL[t + i * 256] = srcL[t + i * 256];
    }
}

__global__ __launch_bounds__(256, 2) void conv_mma_kernel(
    const float* __restrict__ conv_b,
    float* __restrict__ out)
{
    uint32_t* Ah   = s_cv;
    uint32_t* Al   = s_cv + A_WORDS;
    uint32_t* Bbuf = s_cv + 2 * A_WORDS;          // [2][4096]
    float*    S    = reinterpret_cast<float*>(s_cv);

    int t = threadIdx.x, l = t & 31, wid = t >> 5;
    int r    = blockIdx.x;
    int half = blockIdx.y;
    int b    = blockIdx.z;
    int co0  = half * 128;
    int m0   = (wid & 3) * 32;
    int n0h  = wid >> 2;           // 0/1
    int k2l  = l & 3;
    int lq   = l >> 2;

    float acc[2][8][4];
    #pragma unroll
    for (int mt = 0; mt < 2; mt++)
        #pragma unroll
        for (int nt = 0; nt < 8; nt++)
            #pragma unroll
            for (int i = 0; i < 4; i++) acc[mt][nt][i] = 0.f;

    #pragma unroll 1
    for (int chunk = 0; chunk < 8; chunk++) {
        __syncthreads();   // previous chunk's compute done (A + B WAR safe)
        // ---- stage A: 16 c2 x 3 rows x 130 cols ----
        for (int e = t; e < 16 * 3 * 130; e += 256) {
            int c2 = e / 390, rem = e % 390;
            int row = rem / 130, mc = rem % 130;
            int gr = refl(r - 1 + row, NH);
            int gc = refl(mc - 1, NW);
            uint2 v = g_y2[((size_t)(b * 128 + chunk * 16 + c2)) * HWSZ +
                           (size_t)gr * NW + gc];
            int dst = c2 * A_STRIDE + row * 132 + mc;
            Ah[dst] = v.x;
            Al[dst] = v.y;
        }
        stageB(0, chunk, half, Bbuf, t);

        #pragma unroll 1
        for (int tap = 0; tap < 9; tap++) {
            __syncthreads();   // staged data visible; prev-tap reads done
            if (tap < 8) stageB(tap + 1, chunk, half, Bbuf + ((tap + 1) & 1) * B_BUF_WORDS, t);

            const uint32_t* bh = Bbuf + (tap & 1) * B_BUF_WORDS;
            const uint32_t* bl = bh + 2048;
            int dy = tap / 3 - 1, dx = tap % 3 - 1;
            int aoff = (1 + dy) * 132 + 1 + dx;

            #pragma unroll
            for (int kk = 0; kk < 2; kk++) {
                int c2b = kk * 8 + k2l;
                uint32_t ah[2][4], al[2][4];
                #pragma unroll
                for (int mt = 0; mt < 2; mt++) {
                    int base = c2b * A_STRIDE + aoff + m0 + mt * 16 + lq;
                    ah[mt][0] = Ah[base];                  ah[mt][1] = Ah[base + 8];
                    ah[mt][2] = Ah[base + 4 * A_STRIDE];   ah[mt][3] = Ah[base + 4 * A_STRIDE + 8];
                    al[mt][0] = Al[base];                  al[mt][1] = Al[base + 8];
                    al[mt][2] = Al[base + 4 * A_STRIDE];   al[mt][3] = Al[base + 4 * A_STRIDE + 8];
                }
                int bidx = ((kk * 4 + k2l) * 2 + n0h) * 32 + lq;
                #pragma unroll
                for (int ntpair = 0; ntpair < 4; ntpair++) {
                    uint4 h  = reinterpret_cast<const uint4*>(bh)[bidx + ntpair * 8];
                    uint4 lo = reinterpret_cast<const uint4*>(bl)[bidx + ntpair * 8];
                    int ntA = ntpair * 2, ntB = ntA + 1;
                    #pragma unroll
                    for (int mt = 0; mt < 2; mt++) {
                        mma16816(acc[mt][ntA], ah[mt], h.x,  h.y);   // yh*wh
                        mma16816(acc[mt][ntA], al[mt], h.x,  h.y);   // yl*wh
                        mma16816(acc[mt][ntA], ah[mt], lo.x, lo.y);  // yh*wl
                        mma16816(acc[mt][ntB], ah[mt], h.z,  h.w);
                        mma16816(acc[mt][ntB], al[mt], h.z,  h.w);
                        mma16816(acc[mt][ntB], ah[mt], lo.z, lo.w);
                    }
                }
            }
        }
    }

    // ---- epilogue: fragments -> smem [co_local][130+m] -> coalesced GMEM ----
    // co_local = n0h*64 + ntpair*16 + 2*c + (nt&1), D frag cols c = 2*k2l, 2*k2l+1
    __syncthreads();
    #pragma unroll
    for (int mt = 0; mt < 2; mt++) {
        #pragma unroll
        for (int nt = 0; nt < 8; nt++) {
            int m = m0 + mt * 16 + lq;
            int nbase = n0h * 64 + (nt >> 1) * 16 + 4 * k2l + (nt & 1);
            S[nbase * 130 + m]           = acc[mt][nt][0];
            S[(nbase + 2) * 130 + m]     = acc[mt][nt][1];
            S[nbase * 130 + m + 8]       = acc[mt][nt][2];
            S[(nbase + 2) * 130 + m + 8] = acc[mt][nt][3];
        }
    }
    __syncthreads();
    for (int e = t; e < 128 * 128; e += 256) {
        int n = e >> 7, m = e & 127;
        out[((size_t)(b * NOUT + co0 + n)) * HWSZ + (size_t)r * NW + m] =
            S[n * 130 + m] + conv_b[co0 + n];
    }
}

// ============================================================================
extern "C" void kernel_launch(void* const* d_in, const int* in_sizes, int n_in,
                              void* d_out, int out_size) {
    const float* x      = (const float*)d_in[0];
    const float* ws     = (const float*)d_in[1];
    const float* wp     = (const float*)d_in[2];
    const float* bias   = (const float*)d_in[3];
    const float* conv_w = (const float*)d_in[4];
    const float* conv_b = (const float*)d_in[5];
    float* out = (float*)d_out;

    stats_kernel<<<NB * NC, 256>>>(x);
    wprep_kernel<<<dim3(9, 8, 2), 256>>>(conv_w);
    ada_kernel<<<dim3(16, NG, NB), 256>>>(x, ws, wp, bias);

    cudaFuncSetAttribute(conv_mma_kernel,
                         cudaFuncAttributeMaxDynamicSharedMemorySize,
                         CONV_SMEM);
    conv_mma_kernel<<<dim3(NH, 2, NB), 256, CONV_SMEM>>>(conv_b, out);
}

// round 12
// speedup vs baseline: 1.3162x; 1.3162x over previous
#include <cuda_runtime.h>
#include <cuda_fp16.h>
#include <cstdint>

#define NB   8
#define NC   256
#define NH   128
#define NW   128
#define NG   32
#define CPG  8
#define NOUT 256
#define FEPS 1e-5f
#define HWSZ (NH * NW)

// ---------------- device scratch (no-alloc rule: __device__ globals) --------
// y split into fp16 hi/lo, channel-pair packed: uint2 {x = hi pair, y = lo pair}
// layout [b][c2=0..127][pix]
__device__ uint2    g_y2[(size_t)NB * 128 * HWSZ];
__device__ float    g_mean[NB * NC];
__device__ float    g_rstd[NB * NC];
// conv weights (single fp16) pre-permuted into per-thread fragment chunks:
// [tap][cichunk][half][2048 words], word = ((((kk*4+k2l)*2+n0h)*4+ntpair)*8+lq)*4+widx
__device__ uint32_t g_wB[9 * 8 * 2 * 2048];

__device__ __forceinline__ int refl(int i, int n) {
    return i < 0 ? -i : (i >= n ? 2 * n - 2 - i : i);
}

__device__ __forceinline__ void mma16816(float* c, const uint32_t* a,
                                         uint32_t b0, uint32_t b1) {
    asm volatile(
        "mma.sync.aligned.m16n8k16.row.col.f32.f16.f16.f32 "
        "{%0,%1,%2,%3}, {%4,%5,%6,%7}, {%8,%9}, {%0,%1,%2,%3};"
        : "+f"(c[0]), "+f"(c[1]), "+f"(c[2]), "+f"(c[3])
        : "r"(a[0]), "r"(a[1]), "r"(a[2]), "r"(a[3]), "r"(b0), "r"(b1));
}

// ============================================================================
// Kernel 1: per-(b,c) mean / rstd over 128x128 (biased variance)
// ============================================================================
__global__ __launch_bounds__(256) void stats_kernel(const float* __restrict__ x) {
    __shared__ float sh[16];
    int bc = blockIdx.x;
    const float4* xc = reinterpret_cast<const float4*>(x + (size_t)bc * HWSZ);
    float s = 0.f, ss = 0.f;
    for (int i = threadIdx.x; i < HWSZ / 4; i += 256) {
        float4 v = xc[i];
        s  += (v.x + v.y) + (v.z + v.w);
        ss += (v.x * v.x + v.y * v.y) + (v.z * v.z + v.w * v.w);
    }
    #pragma unroll
    for (int o = 16; o > 0; o >>= 1) {
        s  += __shfl_down_sync(0xffffffffu, s,  o);
        ss += __shfl_down_sync(0xffffffffu, ss, o);
    }
    if ((threadIdx.x & 31) == 0) {
        sh[threadIdx.x >> 5]       = s;
        sh[8 + (threadIdx.x >> 5)] = ss;
    }
    __syncthreads();
    if (threadIdx.x == 0) {
        float S = 0.f, SS = 0.f;
        #pragma unroll
        for (int i = 0; i < 8; i++) { S += sh[i]; SS += sh[8 + i]; }
        float m   = S * (1.f / HWSZ);
        float var = SS * (1.f / HWSZ) - m * m;
        g_mean[bc] = m;
        g_rstd[bc] = rsqrtf(var + FEPS);
    }
}

// ============================================================================
// Kernel 1b: quantize (fp16) + permute final-conv weights into fragment order.
// 16B chunk = {w(c2b,coA), w(c2b+4,coA), w(c2b,coA+1), w(c2b+4,coA+1)},
// co = half*128 + n0h*64 + ntpair*16 + 2*lq + (widx>>1).
// ============================================================================
__global__ __launch_bounds__(256) void wprep_kernel(const float* __restrict__ conv_w) {
    int tap     = blockIdx.x;   // 0..8
    int cichunk = blockIdx.y;   // 0..7
    int half    = blockIdx.z;   // 0..1
    size_t base = ((size_t)(tap * 8 + cichunk) * 2 + half) * 2048;
    for (int w = threadIdx.x; w < 2048; w += 256) {
        int widx   = w & 3;
        int lq     = (w >> 2) & 7;
        int ntpair = (w >> 5) & 3;
        int n0h    = (w >> 7) & 1;
        int k2l    = (w >> 8) & 3;
        int kk     = (w >> 10) & 1;
        int c2 = cichunk * 16 + kk * 8 + k2l + ((widx & 1) ? 4 : 0);
        int co = half * 128 + n0h * 64 + ntpair * 16 + 2 * lq + (widx >> 1);
        float w0 = conv_w[((size_t)co * NC + 2 * c2)     * 9 + tap];
        float w1 = conv_w[((size_t)co * NC + 2 * c2 + 1) * 9 + tap];
        __half h0 = __float2half_rn(w0);
        __half h1 = __float2half_rn(w1);
        g_wB[base + w] = (uint32_t)__half_as_ushort(h0) |
                         ((uint32_t)__half_as_ushort(h1) << 16);
    }
}

// ============================================================================
// Kernel 2: fused instance-norm + adaptive grouped 3x3 + folded 1x1 + bias,
//           emitting channel-pair-packed fp16 {hi,lo} uint2.
// ============================================================================
__global__ __launch_bounds__(256, 2) void ada_kernel(
    const float* __restrict__ x,
    const float* __restrict__ ws,    // [B,C,CPG,3,3]
    const float* __restrict__ wp,    // [B,C,CPG,1,1]
    const float* __restrict__ bias)  // [B,C]
{
    __shared__ float tile[CPG][10][132];
    __shared__ float sW[CPG][CPG][9];

    int rt = blockIdx.x;   // 0..15
    int g  = blockIdx.y;
    int b  = blockIdx.z;
    int r0 = rt * 8;
    int t  = threadIdx.x;
    int cbase = b * NC + g * CPG;
    const float* xb = x + (size_t)cbase * HWSZ;

    for (int e = t; e < CPG * CPG * 9; e += 256) {
        int o = e / 72, rem = e % 72, i = rem / 9, k = rem % 9;
        float acc = 0.f;
        #pragma unroll
        for (int m = 0; m < CPG; m++)
            acc += wp[(size_t)(cbase + o) * CPG + m] *
                   ws[((size_t)(cbase + m) * CPG + i) * 9 + k];
        sW[o][i][k] = acc;
    }

    for (int e = t; e < CPG * 10 * 130; e += 256) {
        int ch = e / 1300, rem = e % 1300, tr = rem / 130, tc = rem % 130;
        int gr = refl(r0 - 1 + tr, NH);
        int gc = refl(tc - 1, NW);
        float m  = g_mean[cbase + ch];
        float rs = g_rstd[cbase + ch];
        tile[ch][tr][tc] = (xb[(size_t)ch * HWSZ + gr * NW + gc] - m) * rs;
    }
    __syncthreads();

    int col = t & 127;
    int rq  = t >> 7;
    float acc[CPG][4];
    #pragma unroll
    for (int o = 0; o < CPG; o++)
        #pragma unroll
        for (int r = 0; r < 4; r++) acc[o][r] = 0.f;

    #pragma unroll 1
    for (int i = 0; i < CPG; i++) {
        float v[6][3];
        #pragma unroll
        for (int rr = 0; rr < 6; rr++)
            #pragma unroll
            for (int c3 = 0; c3 < 3; c3++)
                v[rr][c3] = tile[i][rq * 4 + rr][col + c3];
        #pragma unroll
        for (int o = 0; o < CPG; o++) {
            #pragma unroll
            for (int k = 0; k < 9; k++) {
                float w = sW[o][i][k];
                int dy = k / 3, dx = k % 3;
                #pragma unroll
                for (int r = 0; r < 4; r++)
                    acc[o][r] += w * v[r + dy][dx];
            }
        }
    }

    int ccg = g * CPG;
    #pragma unroll
    for (int o = 0; o < CPG; o += 2) {
        float b0v = bias[cbase + o], b1v = bias[cbase + o + 1];
        int c2 = (ccg + o) >> 1;
        #pragma unroll
        for (int r = 0; r < 4; r++) {
            float v0 = acc[o][r] + b0v;
            float v1 = acc[o + 1][r] + b1v;
            __half h0 = __float2half_rn(v0);
            __half h1 = __float2half_rn(v1);
            __half l0 = __float2half_rn(v0 - __half2float(h0));
            __half l1 = __float2half_rn(v1 - __half2float(h1));
            uint2 pk;
            pk.x = (uint32_t)__half_as_ushort(h0) |
                   ((uint32_t)__half_as_ushort(h1) << 16);
            pk.y = (uint32_t)__half_as_ushort(l0) |
                   ((uint32_t)__half_as_ushort(l1) << 16);
            g_y2[((size_t)(b * 128 + c2)) * HWSZ +
                 (size_t)(r0 + rq * 4 + r) * NW + col] = pk;
        }
    }
}

// ============================================================================
// Kernel 3: final 3x3 conv via mma.sync m16n8k16 fp16, 2-term split
// (yh*w + yl*w). CTA = (row r, co-half, batch). 8 warps = 4(M) x 2(N).
// A: im2col per 32-ci chunk, stride 408 (conflict-free frag LDS).
// B: GMEM pre-permuted fp16 chunks (8KB/tap) -> conflict-free LDS.128,
//    double-buffered, one __syncthreads per tap.
// ============================================================================
#define A_STRIDE 408
#define A_WORDS  (16 * A_STRIDE)                  // 6528
#define B_BUF_WORDS 2048                          // fp16: single array
#define CONV_SMEM ((2 * A_WORDS + 2 * B_BUF_WORDS) * 4)   // 68608 bytes

extern __shared__ uint32_t s_cv[];

__device__ __forceinline__ void stageB(int tap, int chunk, int half,
                                       uint32_t* dst, int t) {
    const uint4* src = reinterpret_cast<const uint4*>(
        g_wB + ((size_t)(tap * 8 + chunk) * 2 + half) * 2048);
    uint4* d4 = reinterpret_cast<uint4*>(dst);
    d4[t]       = src[t];
    d4[t + 256] = src[t + 256];
}

__global__ __launch_bounds__(256, 2) void conv_mma_kernel(
    const float* __restrict__ conv_b,
    float* __restrict__ out)
{
    uint32_t* Ah   = s_cv;
    uint32_t* Al   = s_cv + A_WORDS;
    uint32_t* Bbuf = s_cv + 2 * A_WORDS;          // [2][2048]
    float*    S    = reinterpret_cast<float*>(s_cv);

    int t = threadIdx.x, l = t & 31, wid = t >> 5;
    int r    = blockIdx.x;
    int half = blockIdx.y;
    int b    = blockIdx.z;
    int co0  = half * 128;
    int m0   = (wid & 3) * 32;
    int n0h  = wid >> 2;           // 0/1
    int k2l  = l & 3;
    int lq   = l >> 2;

    float acc[2][8][4];
    #pragma unroll
    for (int mt = 0; mt < 2; mt++)
        #pragma unroll
        for (int nt = 0; nt < 8; nt++)
            #pragma unroll
            for (int i = 0; i < 4; i++) acc[mt][nt][i] = 0.f;

    #pragma unroll 1
    for (int chunk = 0; chunk < 8; chunk++) {
        __syncthreads();   // previous chunk's compute done (A + B WAR safe)
        // ---- stage A: 16 c2 x 3 rows x 130 cols (hi & lo fp16 pairs) ----
        for (int e = t; e < 16 * 3 * 130; e += 256) {
            int c2 = e / 390, rem = e % 390;
            int row = rem / 130, mc = rem % 130;
            int gr = refl(r - 1 + row, NH);
            int gc = refl(mc - 1, NW);
            uint2 v = g_y2[((size_t)(b * 128 + chunk * 16 + c2)) * HWSZ +
                           (size_t)gr * NW + gc];
            int dst = c2 * A_STRIDE + row * 132 + mc;
            Ah[dst] = v.x;
            Al[dst] = v.y;
        }
        stageB(0, chunk, half, Bbuf, t);

        #pragma unroll 1
        for (int tap = 0; tap < 9; tap++) {
            __syncthreads();   // staged data visible; prev-tap reads done
            if (tap < 8) stageB(tap + 1, chunk, half, Bbuf + ((tap + 1) & 1) * B_BUF_WORDS, t);

            const uint32_t* bh = Bbuf + (tap & 1) * B_BUF_WORDS;
            int dy = tap / 3 - 1, dx = tap % 3 - 1;
            int aoff = (1 + dy) * 132 + 1 + dx;

            #pragma unroll
            for (int kk = 0; kk < 2; kk++) {
                int c2b = kk * 8 + k2l;
                uint32_t ah[2][4], al[2][4];
                #pragma unroll
                for (int mt = 0; mt < 2; mt++) {
                    int base = c2b * A_STRIDE + aoff + m0 + mt * 16 + lq;
                    ah[mt][0] = Ah[base];                  ah[mt][1] = Ah[base + 8];
                    ah[mt][2] = Ah[base + 4 * A_STRIDE];   ah[mt][3] = Ah[base + 4 * A_STRIDE + 8];
                    al[mt][0] = Al[base];                  al[mt][1] = Al[base + 8];
                    al[mt][2] = Al[base + 4 * A_STRIDE];   al[mt][3] = Al[base + 4 * A_STRIDE + 8];
                }
                int bidx = ((kk * 4 + k2l) * 2 + n0h) * 32 + lq;
                #pragma unroll
                for (int ntpair = 0; ntpair < 4; ntpair++) {
                    uint4 h = reinterpret_cast<const uint4*>(bh)[bidx + ntpair * 8];
                    int ntA = ntpair * 2, ntB = ntA + 1;
                    #pragma unroll
                    for (int mt = 0; mt < 2; mt++) {
                        mma16816(acc[mt][ntA], ah[mt], h.x, h.y);   // yh*w
                        mma16816(acc[mt][ntA], al[mt], h.x, h.y);   // yl*w
                        mma16816(acc[mt][ntB], ah[mt], h.z, h.w);
                        mma16816(acc[mt][ntB], al[mt], h.z, h.w);
                    }
                }
            }
        }
    }

    // ---- epilogue: fragments -> smem [co_local][130+m] -> coalesced GMEM ----
    // co_local = n0h*64 + ntpair*16 + 4*k2l + (nt&1); acc cols -> +0/+2
    __syncthreads();
    #pragma unroll
    for (int mt = 0; mt < 2; mt++) {
        #pragma unroll
        for (int nt = 0; nt < 8; nt++) {
            int m = m0 + mt * 16 + lq;
            int nbase = n0h * 64 + (nt >> 1) * 16 + 4 * k2l + (nt & 1);
            S[nbase * 130 + m]           = acc[mt][nt][0];
            S[(nbase + 2) * 130 + m]     = acc[mt][nt][1];
            S[nbase * 130 + m + 8]       = acc[mt][nt][2];
            S[(nbase + 2) * 130 + m + 8] = acc[mt][nt][3];
        }
    }
    __syncthreads();
    for (int e = t; e < 128 * 128; e += 256) {
        int n = e >> 7, m = e & 127;
        out[((size_t)(b * NOUT + co0 + n)) * HWSZ + (size_t)r * NW + m] =
            S[n * 130 + m] + conv_b[co0 + n];
    }
}

// ============================================================================
extern "C" void kernel_launch(void* const* d_in, const int* in_sizes, int n_in,
                              void* d_out, int out_size) {
    const float* x      = (const float*)d_in[0];
    const float* ws     = (const float*)d_in[1];
    const float* wp     = (const float*)d_in[2];
    const float* bias   = (const float*)d_in[3];
    const float* conv_w = (const float*)d_in[4];
    const float* conv_b = (const float*)d_in[5];
    float* out = (float*)d_out;

    stats_kernel<<<NB * NC, 256>>>(x);
    wprep_kernel<<<dim3(9, 8, 2), 256>>>(conv_w);
    ada_kernel<<<dim3(16, NG, NB), 256>>>(x, ws, wp, bias);

    cudaFuncSetAttribute(conv_mma_kernel,
                         cudaFuncAttributeMaxDynamicSharedMemorySize,
                         CONV_SMEM);
    conv_mma_kernel<<<dim3(NH, 2, NB), 256, CONV_SMEM>>>(conv_b, out);
}

// round 15
// speedup vs baseline: 1.6189x; 1.2299x over previous
#include <cuda_runtime.h>
#include <cuda_fp16.h>
#include <cstdint>

#define NB   8
#define NC   256
#define NH   128
#define NW   128
#define NG   32
#define CPG  8
#define NOUT 256
#define FEPS 1e-5f
#define HWSZ (NH * NW)

// ---------------- device scratch (no-alloc rule: __device__ globals) --------
// y quantized to fp16, channel-pair packed: u32 = {h(c even) lo16, h(c odd) hi16}
// layout [b][c2=0..127][pix]
__device__ uint32_t g_yh[(size_t)NB * 128 * HWSZ];
__device__ float    g_mean[NB * NC];
__device__ float    g_rstd[NB * NC];
// conv weights (fp16) pre-permuted into per-thread fragment chunks:
// [tap][cichunk][half][2048 words], word = ((((kk*4+k2l)*2+n0h)*4+ntpair)*8+lq)*4+widx
__device__ uint32_t g_wB[9 * 8 * 2 * 2048];

__device__ __forceinline__ int refl(int i, int n) {
    return i < 0 ? -i : (i >= n ? 2 * n - 2 - i : i);
}

__device__ __forceinline__ void mma16816(float* c, const uint32_t* a,
                                         uint32_t b0, uint32_t b1) {
    asm volatile(
        "mma.sync.aligned.m16n8k16.row.col.f32.f16.f16.f32 "
        "{%0,%1,%2,%3}, {%4,%5,%6,%7}, {%8,%9}, {%0,%1,%2,%3};"
        : "+f"(c[0]), "+f"(c[1]), "+f"(c[2]), "+f"(c[3])
        : "r"(a[0]), "r"(a[1]), "r"(a[2]), "r"(a[3]), "r"(b0), "r"(b1));
}

// ============================================================================
// Kernel 1: per-(b,c) mean / rstd over 128x128 (biased variance)
// ============================================================================
__global__ __launch_bounds__(256) void stats_kernel(const float* __restrict__ x) {
    __shared__ float sh[16];
    int bc = blockIdx.x;
    const float4* xc = reinterpret_cast<const float4*>(x + (size_t)bc * HWSZ);
    float s = 0.f, ss = 0.f;
    for (int i = threadIdx.x; i < HWSZ / 4; i += 256) {
        float4 v = xc[i];
        s  += (v.x + v.y) + (v.z + v.w);
        ss += (v.x * v.x + v.y * v.y) + (v.z * v.z + v.w * v.w);
    }
    #pragma unroll
    for (int o = 16; o > 0; o >>= 1) {
        s  += __shfl_down_sync(0xffffffffu, s,  o);
        ss += __shfl_down_sync(0xffffffffu, ss, o);
    }
    if ((threadIdx.x & 31) == 0) {
        sh[threadIdx.x >> 5]       = s;
        sh[8 + (threadIdx.x >> 5)] = ss;
    }
    __syncthreads();
    if (threadIdx.x == 0) {
        float S = 0.f, SS = 0.f;
        #pragma unroll
        for (int i = 0; i < 8; i++) { S += sh[i]; SS += sh[8 + i]; }
        float m   = S * (1.f / HWSZ);
        float var = SS * (1.f / HWSZ) - m * m;
        g_mean[bc] = m;
        g_rstd[bc] = rsqrtf(var + FEPS);
    }
}

// ============================================================================
// Kernel 1b: quantize (fp16) + permute final-conv weights into fragment order.
// 16B chunk = {w(c2b,coA), w(c2b+4,coA), w(c2b,coA+1), w(c2b+4,coA+1)},
// co = half*128 + n0h*64 + ntpair*16 + 2*lq + (widx>>1).
// ============================================================================
__global__ __launch_bounds__(256) void wprep_kernel(const float* __restrict__ conv_w) {
    int tap     = blockIdx.x;   // 0..8
    int cichunk = blockIdx.y;   // 0..7
    int half    = blockIdx.z;   // 0..1
    size_t base = ((size_t)(tap * 8 + cichunk) * 2 + half) * 2048;
    for (int w = threadIdx.x; w < 2048; w += 256) {
        int widx   = w & 3;
        int lq     = (w >> 2) & 7;
        int ntpair = (w >> 5) & 3;
        int n0h    = (w >> 7) & 1;
        int k2l    = (w >> 8) & 3;
        int kk     = (w >> 10) & 1;
        int c2 = cichunk * 16 + kk * 8 + k2l + ((widx & 1) ? 4 : 0);
        int co = half * 128 + n0h * 64 + ntpair * 16 + 2 * lq + (widx >> 1);
        float w0 = conv_w[((size_t)co * NC + 2 * c2)     * 9 + tap];
        float w1 = conv_w[((size_t)co * NC + 2 * c2 + 1) * 9 + tap];
        __half h0 = __float2half_rn(w0);
        __half h1 = __float2half_rn(w1);
        g_wB[base + w] = (uint32_t)__half_as_ushort(h0) |
                         ((uint32_t)__half_as_ushort(h1) << 16);
    }
}

// ============================================================================
// Kernel 2: fused instance-norm + adaptive grouped 3x3 + folded 1x1 + bias,
//           emitting channel-pair-packed fp16 output.
// ============================================================================
__global__ __launch_bounds__(256, 2) void ada_kernel(
    const float* __restrict__ x,
    const float* __restrict__ ws,    // [B,C,CPG,3,3]
    const float* __restrict__ wp,    // [B,C,CPG,1,1]
    const float* __restrict__ bias)  // [B,C]
{
    __shared__ float tile[CPG][10][132];
    __shared__ float sW[CPG][CPG][9];

    int rt = blockIdx.x;   // 0..15
    int g  = blockIdx.y;
    int b  = blockIdx.z;
    int r0 = rt * 8;
    int t  = threadIdx.x;
    int cbase = b * NC + g * CPG;
    const float* xb = x + (size_t)cbase * HWSZ;

    for (int e = t; e < CPG * CPG * 9; e += 256) {
        int o = e / 72, rem = e % 72, i = rem / 9, k = rem % 9;
        float acc = 0.f;
        #pragma unroll
        for (int m = 0; m < CPG; m++)
            acc += wp[(size_t)(cbase + o) * CPG + m] *
                   ws[((size_t)(cbase + m) * CPG + i) * 9 + k];
        sW[o][i][k] = acc;
    }

    for (int e = t; e < CPG * 10 * 130; e += 256) {
        int ch = e / 1300, rem = e % 1300, tr = rem / 130, tc = rem % 130;
        int gr = refl(r0 - 1 + tr, NH);
        int gc = refl(tc - 1, NW);
        float m  = g_mean[cbase + ch];
        float rs = g_rstd[cbase + ch];
        tile[ch][tr][tc] = (xb[(size_t)ch * HWSZ + gr * NW + gc] - m) * rs;
    }
    __syncthreads();

    int col = t & 127;
    int rq  = t >> 7;
    float acc[CPG][4];
    #pragma unroll
    for (int o = 0; o < CPG; o++)
        #pragma unroll
        for (int r = 0; r < 4; r++) acc[o][r] = 0.f;

    #pragma unroll 1
    for (int i = 0; i < CPG; i++) {
        float v[6][3];
        #pragma unroll
        for (int rr = 0; rr < 6; rr++)
            #pragma unroll
            for (int c3 = 0; c3 < 3; c3++)
                v[rr][c3] = tile[i][rq * 4 + rr][col + c3];
        #pragma unroll
        for (int o = 0; o < CPG; o++) {
            #pragma unroll
            for (int k = 0; k < 9; k++) {
                float w = sW[o][i][k];
                int dy = k / 3, dx = k % 3;
                #pragma unroll
                for (int r = 0; r < 4; r++)
                    acc[o][r] += w * v[r + dy][dx];
            }
        }
    }

    int ccg = g * CPG;
    #pragma unroll
    for (int o = 0; o < CPG; o += 2) {
        float b0v = bias[cbase + o], b1v = bias[cbase + o + 1];
        int c2 = (ccg + o) >> 1;
        #pragma unroll
        for (int r = 0; r < 4; r++) {
            float v0 = acc[o][r] + b0v;
            float v1 = acc[o + 1][r] + b1v;
            __half h0 = __float2half_rn(v0);
            __half h1 = __float2half_rn(v1);
            g_yh[((size_t)(b * 128 + c2)) * HWSZ +
                 (size_t)(r0 + rq * 4 + r) * NW + col] =
                (uint32_t)__half_as_ushort(h0) |
                ((uint32_t)__half_as_ushort(h1) << 16);
        }
    }
}

// ============================================================================
// Kernel 3: final 3x3 conv via mma.sync m16n8k16 fp16 (single term).
// CTA = (row r, co-half, batch). 8 warps = 4(M) x 2(N).
// A: im2col per 32-ci chunk, stride 408, conflict-free frag LDS.
// B: register-prefetched one tap ahead (LDG latency overlaps MMA work),
//    STS into double buffer at tap top, ONE __syncthreads per tap.
// SMEM sized by the EPILOGUE reuse (128*130 floats = 66560 B), which exceeds
// the 42496 B staging footprint — this was the R14 OOB.
// ============================================================================
#define A_STRIDE 408
#define A_WORDS  (16 * A_STRIDE)                  // 6528
#define B_BUF_WORDS 2048
#define STAGE_BYTES ((A_WORDS + 2 * B_BUF_WORDS) * 4)   // 42496
#define EPI_BYTES   (128 * 130 * 4)                     // 66560
#define CONV_SMEM   EPI_BYTES                           // max(42496, 66560)

extern __shared__ uint32_t s_cv[];

__device__ __forceinline__ void prefB(int tap, int chunk, int half,
                                      uint4* pb, int t) {
    const uint4* src = reinterpret_cast<const uint4*>(
        g_wB + ((size_t)(tap * 8 + chunk) * 2 + half) * 2048);
    pb[0] = src[t];
    pb[1] = src[t + 256];
}

__global__ __launch_bounds__(256, 2) void conv_mma_kernel(
    const float* __restrict__ conv_b,
    float* __restrict__ out)
{
    uint32_t* Ah   = s_cv;
    uint32_t* Bbuf = s_cv + A_WORDS;              // [2][2048]
    float*    S    = reinterpret_cast<float*>(s_cv);

    int t = threadIdx.x, l = t & 31, wid = t >> 5;
    int r    = blockIdx.x;
    int half = blockIdx.y;
    int b    = blockIdx.z;
    int co0  = half * 128;
    int m0   = (wid & 3) * 32;
    int n0h  = wid >> 2;           // 0/1
    int k2l  = l & 3;
    int lq   = l >> 2;

    float acc[2][8][4];
    #pragma unroll
    for (int mt = 0; mt < 2; mt++)
        #pragma unroll
        for (int nt = 0; nt < 8; nt++)
            #pragma unroll
            for (int i = 0; i < 4; i++) acc[mt][nt][i] = 0.f;

    uint4 pb[2];
    prefB(0, 0, half, pb, t);   // prefetch tap 0 of chunk 0

    #pragma unroll 1
    for (int chunk = 0; chunk < 8; chunk++) {
        __syncthreads();   // prev chunk's A/B reads done (WAR safe)
        // ---- stage A: 16 c2 x 3 rows x 130 cols (fp16 pairs) ----
        for (int e = t; e < 16 * 3 * 130; e += 256) {
            int c2 = e / 390, rem = e % 390;
            int row = rem / 130, mc = rem % 130;
            int gr = refl(r - 1 + row, NH);
            int gc = refl(mc - 1, NW);
            Ah[c2 * A_STRIDE + row * 132 + mc] =
                g_yh[((size_t)(b * 128 + chunk * 16 + c2)) * HWSZ +
                     (size_t)gr * NW + gc];
        }

        #pragma unroll 1
        for (int tap = 0; tap < 9; tap++) {
            // commit prefetched B tile into its buffer
            {
                uint4* d4 = reinterpret_cast<uint4*>(Bbuf + (tap & 1) * B_BUF_WORDS);
                d4[t]       = pb[0];
                d4[t + 256] = pb[1];
            }
            __syncthreads();   // staged A (tap 0) + B visible; prev reads done
            // prefetch next tile (LDG latency overlaps the MMAs below)
            if (tap < 8)            prefB(tap + 1, chunk, half, pb, t);
            else if (chunk < 7)     prefB(0, chunk + 1, half, pb, t);

            const uint32_t* bh = Bbuf + (tap & 1) * B_BUF_WORDS;
            int dy = tap / 3 - 1, dx = tap % 3 - 1;
            int aoff = (1 + dy) * 132 + 1 + dx;

            #pragma unroll
            for (int kk = 0; kk < 2; kk++) {
                int c2b = kk * 8 + k2l;
                uint32_t ah[2][4];
                #pragma unroll
                for (int mt = 0; mt < 2; mt++) {
                    int base = c2b * A_STRIDE + aoff + m0 + mt * 16 + lq;
                    ah[mt][0] = Ah[base];                  ah[mt][1] = Ah[base + 8];
                    ah[mt][2] = Ah[base + 4 * A_STRIDE];   ah[mt][3] = Ah[base + 4 * A_STRIDE + 8];
                }
                int bidx = ((kk * 4 + k2l) * 2 + n0h) * 32 + lq;
                #pragma unroll
                for (int ntpair = 0; ntpair < 4; ntpair++) {
                    uint4 h = reinterpret_cast<const uint4*>(bh)[bidx + ntpair * 8];
                    int ntA = ntpair * 2, ntB = ntA + 1;
                    #pragma unroll
                    for (int mt = 0; mt < 2; mt++) {
                        mma16816(acc[mt][ntA], ah[mt], h.x, h.y);
                        mma16816(acc[mt][ntB], ah[mt], h.z, h.w);
                    }
                }
            }
        }
    }

    // ---- epilogue: fragments -> smem [co_local][130+m] -> coalesced GMEM ----
    // co_local = n0h*64 + (nt>>1)*16 + 4*k2l + (nt&1); acc cols -> +0/+2
    __syncthreads();
    #pragma unroll
    for (int mt = 0; mt < 2; mt++) {
        #pragma unroll
        for (int nt = 0; nt < 8; nt++) {
            int m = m0 + mt * 16 + lq;
            int nbase = n0h * 64 + (nt >> 1) * 16 + 4 * k2l + (nt & 1);
            S[nbase * 130 + m]           = acc[mt][nt][0];
            S[(nbase + 2) * 130 + m]     = acc[mt][nt][1];
            S[nbase * 130 + m + 8]       = acc[mt][nt][2];
            S[(nbase + 2) * 130 + m + 8] = acc[mt][nt][3];
        }
    }
    __syncthreads();
    for (int e = t; e < 128 * 128; e += 256) {
        int n = e >> 7, m = e & 127;
        out[((size_t)(b * NOUT + co0 + n)) * HWSZ + (size_t)r * NW + m] =
            S[n * 130 + m] + conv_b[co0 + n];
    }
}

// ============================================================================
extern "C" void kernel_launch(void* const* d_in, const int* in_sizes, int n_in,
                              void* d_out, int out_size) {
    const float* x      = (const float*)d_in[0];
    const float* ws     = (const float*)d_in[1];
    const float* wp     = (const float*)d_in[2];
    const float* bias   = (const float*)d_in[3];
    const float* conv_w = (const float*)d_in[4];
    const float* conv_b = (const float*)d_in[5];
    float* out = (float*)d_out;

    stats_kernel<<<NB * NC, 256>>>(x);
    wprep_kernel<<<dim3(9, 8, 2), 256>>>(conv_w);
    ada_kernel<<<dim3(16, NG, NB), 256>>>(x, ws, wp, bias);

    cudaFuncSetAttribute(conv_mma_kernel,
                         cudaFuncAttributeMaxDynamicSharedMemorySize,
                         CONV_SMEM);
    conv_mma_kernel<<<dim3(NH, 2, NB), 256, CONV_SMEM>>>(conv_b, out);
}

// round 16
// speedup vs baseline: 1.7118x; 1.0574x over previous
#include <cuda_runtime.h>
#include <cuda_fp16.h>
#include <cstdint>

#define NB   8
#define NC   256
#define NH   128
#define NW   128
#define NG   32
#define CPG  8
#define NOUT 256
#define FEPS 1e-5f
#define HWSZ (NH * NW)

// ---------------- device scratch (no-alloc rule: __device__ globals) --------
// y quantized to fp16, channel-pair packed: u32 = {h(c even) lo16, h(c odd) hi16}
// layout [b][c2=0..127][pix]
__device__ uint32_t g_yh[(size_t)NB * 128 * HWSZ];
__device__ float    g_mean[NB * NC];
__device__ float    g_rstd[NB * NC];
// conv weights (fp16) pre-permuted into per-thread fragment chunks:
// [tap][cichunk][half][2048 words], word = ((((kk*4+k2l)*2+n0h)*4+ntpair)*8+lq)*4+widx
// -> per-thread uint4 fragments readable DIRECTLY from GMEM (L2-resident).
__device__ uint32_t g_wB[9 * 8 * 2 * 2048];

__device__ __forceinline__ int refl(int i, int n) {
    return i < 0 ? -i : (i >= n ? 2 * n - 2 - i : i);
}

__device__ __forceinline__ void mma16816(float* c, const uint32_t* a,
                                         uint32_t b0, uint32_t b1) {
    asm volatile(
        "mma.sync.aligned.m16n8k16.row.col.f32.f16.f16.f32 "
        "{%0,%1,%2,%3}, {%4,%5,%6,%7}, {%8,%9}, {%0,%1,%2,%3};"
        : "+f"(c[0]), "+f"(c[1]), "+f"(c[2]), "+f"(c[3])
        : "r"(a[0]), "r"(a[1]), "r"(a[2]), "r"(a[3]), "r"(b0), "r"(b1));
}

// ============================================================================
// Kernel 1: per-(b,c) mean / rstd over 128x128 (biased variance)
// ============================================================================
__global__ __launch_bounds__(256) void stats_kernel(const float* __restrict__ x) {
    __shared__ float sh[16];
    int bc = blockIdx.x;
    const float4* xc = reinterpret_cast<const float4*>(x + (size_t)bc * HWSZ);
    float s = 0.f, ss = 0.f;
    for (int i = threadIdx.x; i < HWSZ / 4; i += 256) {
        float4 v = xc[i];
        s  += (v.x + v.y) + (v.z + v.w);
        ss += (v.x * v.x + v.y * v.y) + (v.z * v.z + v.w * v.w);
    }
    #pragma unroll
    for (int o = 16; o > 0; o >>= 1) {
        s  += __shfl_down_sync(0xffffffffu, s,  o);
        ss += __shfl_down_sync(0xffffffffu, ss, o);
    }
    if ((threadIdx.x & 31) == 0) {
        sh[threadIdx.x >> 5]       = s;
        sh[8 + (threadIdx.x >> 5)] = ss;
    }
    __syncthreads();
    if (threadIdx.x == 0) {
        float S = 0.f, SS = 0.f;
        #pragma unroll
        for (int i = 0; i < 8; i++) { S += sh[i]; SS += sh[8 + i]; }
        float m   = S * (1.f / HWSZ);
        float var = SS * (1.f / HWSZ) - m * m;
        g_mean[bc] = m;
        g_rstd[bc] = rsqrtf(var + FEPS);
    }
}

// ============================================================================
// Kernel 1b: quantize (fp16) + permute final-conv weights into fragment order.
// 16B chunk = {w(c2b,coA), w(c2b+4,coA), w(c2b,coA+1), w(c2b+4,coA+1)},
// co = half*128 + n0h*64 + ntpair*16 + 2*lq + (widx>>1).
// ============================================================================
__global__ __launch_bounds__(256) void wprep_kernel(const float* __restrict__ conv_w) {
    int tap     = blockIdx.x;   // 0..8
    int cichunk = blockIdx.y;   // 0..7
    int half    = blockIdx.z;   // 0..1
    size_t base = ((size_t)(tap * 8 + cichunk) * 2 + half) * 2048;
    for (int w = threadIdx.x; w < 2048; w += 256) {
        int widx   = w & 3;
        int lq     = (w >> 2) & 7;
        int ntpair = (w >> 5) & 3;
        int n0h    = (w >> 7) & 1;
        int k2l    = (w >> 8) & 3;
        int kk     = (w >> 10) & 1;
        int c2 = cichunk * 16 + kk * 8 + k2l + ((widx & 1) ? 4 : 0);
        int co = half * 128 + n0h * 64 + ntpair * 16 + 2 * lq + (widx >> 1);
        float w0 = conv_w[((size_t)co * NC + 2 * c2)     * 9 + tap];
        float w1 = conv_w[((size_t)co * NC + 2 * c2 + 1) * 9 + tap];
        __half h0 = __float2half_rn(w0);
        __half h1 = __float2half_rn(w1);
        g_wB[base + w] = (uint32_t)__half_as_ushort(h0) |
                         ((uint32_t)__half_as_ushort(h1) << 16);
    }
}

// ============================================================================
// Kernel 2: fused instance-norm + adaptive grouped 3x3 + folded 1x1 + bias,
//           emitting channel-pair-packed fp16 output.
// ============================================================================
__global__ __launch_bounds__(256, 2) void ada_kernel(
    const float* __restrict__ x,
    const float* __restrict__ ws,    // [B,C,CPG,3,3]
    const float* __restrict__ wp,    // [B,C,CPG,1,1]
    const float* __restrict__ bias)  // [B,C]
{
    __shared__ float tile[CPG][10][132];
    __shared__ float sW[CPG][CPG][9];

    int rt = blockIdx.x;   // 0..15
    int g  = blockIdx.y;
    int b  = blockIdx.z;
    int r0 = rt * 8;
    int t  = threadIdx.x;
    int cbase = b * NC + g * CPG;
    const float* xb = x + (size_t)cbase * HWSZ;

    for (int e = t; e < CPG * CPG * 9; e += 256) {
        int o = e / 72, rem = e % 72, i = rem / 9, k = rem % 9;
        float acc = 0.f;
        #pragma unroll
        for (int m = 0; m < CPG; m++)
            acc += wp[(size_t)(cbase + o) * CPG + m] *
                   ws[((size_t)(cbase + m) * CPG + i) * 9 + k];
        sW[o][i][k] = acc;
    }

    for (int e = t; e < CPG * 10 * 130; e += 256) {
        int ch = e / 1300, rem = e % 1300, tr = rem / 130, tc = rem % 130;
        int gr = refl(r0 - 1 + tr, NH);
        int gc = refl(tc - 1, NW);
        float m  = g_mean[cbase + ch];
        float rs = g_rstd[cbase + ch];
        tile[ch][tr][tc] = (xb[(size_t)ch * HWSZ + gr * NW + gc] - m) * rs;
    }
    __syncthreads();

    int col = t & 127;
    int rq  = t >> 7;
    float acc[CPG][4];
    #pragma unroll
    for (int o = 0; o < CPG; o++)
        #pragma unroll
        for (int r = 0; r < 4; r++) acc[o][r] = 0.f;

    #pragma unroll 1
    for (int i = 0; i < CPG; i++) {
        float v[6][3];
        #pragma unroll
        for (int rr = 0; rr < 6; rr++)
            #pragma unroll
            for (int c3 = 0; c3 < 3; c3++)
                v[rr][c3] = tile[i][rq * 4 + rr][col + c3];
        #pragma unroll
        for (int o = 0; o < CPG; o++) {
            #pragma unroll
            for (int k = 0; k < 9; k++) {
                float w = sW[o][i][k];
                int dy = k / 3, dx = k % 3;
                #pragma unroll
                for (int r = 0; r < 4; r++)
                    acc[o][r] += w * v[r + dy][dx];
            }
        }
    }

    int ccg = g * CPG;
    #pragma unroll
    for (int o = 0; o < CPG; o += 2) {
        float b0v = bias[cbase + o], b1v = bias[cbase + o + 1];
        int c2 = (ccg + o) >> 1;
        #pragma unroll
        for (int r = 0; r < 4; r++) {
            float v0 = acc[o][r] + b0v;
            float v1 = acc[o + 1][r] + b1v;
            __half h0 = __float2half_rn(v0);
            __half h1 = __float2half_rn(v1);
            g_yh[((size_t)(b * 128 + c2)) * HWSZ +
                 (size_t)(r0 + rq * 4 + r) * NW + col] =
                (uint32_t)__half_as_ushort(h0) |
                ((uint32_t)__half_as_ushort(h1) << 16);
        }
    }
}

// ============================================================================
// Kernel 3: final 3x3 conv via mma.sync m16n8k16 fp16.
// CTA = (row r, co-half, batch). 8 warps = 4(M) x 2(N).
// A: im2col per 32-ci chunk in smem, stride 408, conflict-free frag LDS.
// B: NO smem — per-thread uint4 fragments LDG'd directly from the permuted
//    GMEM layout (L2-resident, coalesced per quarter-warp). Removes the B
//    STS commit and ALL per-tap barriers (2 syncs per chunk, A only).
// SMEM sized by epilogue reuse (128*130 floats).
// ============================================================================
#define A_STRIDE 408
#define A_WORDS  (16 * A_STRIDE)                  // 6528
#define EPI_BYTES (128 * 130 * 4)                 // 66560
#define CONV_SMEM EPI_BYTES

extern __shared__ uint32_t s_cv[];

__global__ __launch_bounds__(256, 2) void conv_mma_kernel(
    const float* __restrict__ conv_b,
    float* __restrict__ out)
{
    uint32_t* Ah = s_cv;
    float*    S  = reinterpret_cast<float*>(s_cv);

    int t = threadIdx.x, l = t & 31, wid = t >> 5;
    int r    = blockIdx.x;
    int half = blockIdx.y;
    int b    = blockIdx.z;
    int co0  = half * 128;
    int m0   = (wid & 3) * 32;
    int n0h  = wid >> 2;           // 0/1
    int k2l  = l & 3;
    int lq   = l >> 2;

    // per-thread B fragment offsets (uint4 units) within one (tap,chunk,half) tile
    int boff0 = ((0 * 4 + k2l) * 2 + n0h) * 32 + lq;   // kk = 0
    int boff1 = ((1 * 4 + k2l) * 2 + n0h) * 32 + lq;   // kk = 1

    float acc[2][8][4];
    #pragma unroll
    for (int mt = 0; mt < 2; mt++)
        #pragma unroll
        for (int nt = 0; nt < 8; nt++)
            #pragma unroll
            for (int i = 0; i < 4; i++) acc[mt][nt][i] = 0.f;

    #pragma unroll 1
    for (int chunk = 0; chunk < 8; chunk++) {
        __syncthreads();   // prev chunk's A reads done (WAR safe)
        // ---- stage A: 16 c2 x 3 rows x 130 cols (fp16 pairs) ----
        for (int e = t; e < 16 * 3 * 130; e += 256) {
            int c2 = e / 390, rem = e % 390;
            int row = rem / 130, mc = rem % 130;
            int gr = refl(r - 1 + row, NH);
            int gc = refl(mc - 1, NW);
            Ah[c2 * A_STRIDE + row * 132 + mc] =
                g_yh[((size_t)(b * 128 + chunk * 16 + c2)) * HWSZ +
                     (size_t)gr * NW + gc];
        }
        __syncthreads();   // A visible

        #pragma unroll 1
        for (int tap = 0; tap < 9; tap++) {
            // ---- B fragments: direct LDG (8 independent LDG.128, MLP=8) ----
            const uint4* wsrc = reinterpret_cast<const uint4*>(
                g_wB + ((size_t)(tap * 8 + chunk) * 2 + half) * 2048);
            uint4 Bf[8];
            #pragma unroll
            for (int ntpair = 0; ntpair < 4; ntpair++) {
                Bf[ntpair]     = wsrc[boff0 + ntpair * 8];
                Bf[4 + ntpair] = wsrc[boff1 + ntpair * 8];
            }

            int dy = tap / 3 - 1, dx = tap % 3 - 1;
            int aoff = (1 + dy) * 132 + 1 + dx;

            #pragma unroll
            for (int kk = 0; kk < 2; kk++) {
                int c2b = kk * 8 + k2l;
                uint32_t ah[2][4];
                #pragma unroll
                for (int mt = 0; mt < 2; mt++) {
                    int base = c2b * A_STRIDE + aoff + m0 + mt * 16 + lq;
                    ah[mt][0] = Ah[base];                  ah[mt][1] = Ah[base + 8];
                    ah[mt][2] = Ah[base + 4 * A_STRIDE];   ah[mt][3] = Ah[base + 4 * A_STRIDE + 8];
                }
                #pragma unroll
                for (int ntpair = 0; ntpair < 4; ntpair++) {
                    uint4 h = Bf[kk * 4 + ntpair];
                    int ntA = ntpair * 2, ntB = ntA + 1;
                    #pragma unroll
                    for (int mt = 0; mt < 2; mt++) {
                        mma16816(acc[mt][ntA], ah[mt], h.x, h.y);
                        mma16816(acc[mt][ntB], ah[mt], h.z, h.w);
                    }
                }
            }
        }
    }

    // ---- epilogue: fragments -> smem [co_local][130+m] -> coalesced GMEM ----
    // co_local = n0h*64 + (nt>>1)*16 + 4*k2l + (nt&1); acc cols -> +0/+2
    __syncthreads();
    #pragma unroll
    for (int mt = 0; mt < 2; mt++) {
        #pragma unroll
        for (int nt = 0; nt < 8; nt++) {
            int m = m0 + mt * 16 + lq;
            int nbase = n0h * 64 + (nt >> 1) * 16 + 4 * k2l + (nt & 1);
            S[nbase * 130 + m]           = acc[mt][nt][0];
            S[(nbase + 2) * 130 + m]     = acc[mt][nt][1];
            S[nbase * 130 + m + 8]       = acc[mt][nt][2];
            S[(nbase + 2) * 130 + m + 8] = acc[mt][nt][3];
        }
    }
    __syncthreads();
    for (int e = t; e < 128 * 128; e += 256) {
        int n = e >> 7, m = e & 127;
        out[((size_t)(b * NOUT + co0 + n)) * HWSZ + (size_t)r * NW + m] =
            S[n * 130 + m] + conv_b[co0 + n];
    }
}

// ============================================================================
extern "C" void kernel_launch(void* const* d_in, const int* in_sizes, int n_in,
                              void* d_out, int out_size) {
    const float* x      = (const float*)d_in[0];
    const float* ws     = (const float*)d_in[1];
    const float* wp     = (const float*)d_in[2];
    const float* bias   = (const float*)d_in[3];
    const float* conv_w = (const float*)d_in[4];
    const float* conv_b = (const float*)d_in[5];
    float* out = (float*)d_out;

    stats_kernel<<<NB * NC, 256>>>(x);
    wprep_kernel<<<dim3(9, 8, 2), 256>>>(conv_w);
    ada_kernel<<<dim3(16, NG, NB), 256>>>(x, ws, wp, bias);

    cudaFuncSetAttribute(conv_mma_kernel,
                         cudaFuncAttributeMaxDynamicSharedMemorySize,
                         CONV_SMEM);
    conv_mma_kernel<<<dim3(NH, 2, NB), 256, CONV_SMEM>>>(conv_b, out);
}